// round 7
// baseline (speedup 1.0000x reference)
#include <cuda_runtime.h>
#include <cstdint>

// Problem dims
#define BDIM 64
#define TDIM 512
#define KDIM 1024   // IN_DIM
#define HDIM 1024   // HID
#define MTOT (BDIM * TDIM)   // 32768 rows of the GEMM

// exp(-1/20) rounded to nearest fp32
#define ALPHA 0.9512294245007140f

// Scratch for I = x @ W^T + b   (128 MB, static device allocation — guard-safe)
__device__ float g_I[(size_t)MTOT * HDIM];

// ---------------------------------------------------------------------------
// SGEMM (NT), Eigen-gebp-ordered accumulation with kc = 1016:
// Eigen ARM64 defaults use l1 = 64KB (Neoverse/Apple bump), so the
// multithreaded blocking gives k_cache = (65536-192)/64 = 1021 -> kc = 1016.
//   C[m,n] = (s1 + s2) + bias[n],  s1 = in-order fma chain k=[0,1016),
//                                  s2 = in-order fma chain k=[1016,1024)
// folded with single FADDs (Eigen gebp C-buffer accumulate; C pre-zeroed so
// the first fold is exact).
// BM=128, BN=128, BK=8, TM=TN=8, 256 threads.
// ---------------------------------------------------------------------------
constexpr int BM = 128, BN = 128, BK = 8, TM = 8, TN = 8;

__global__ __launch_bounds__(256, 1) void sgemm_nt_bias_eigen(
    const float* __restrict__ A,      // [MTOT, KDIM] row-major
    const float* __restrict__ W,      // [HDIM, KDIM] row-major
    const float* __restrict__ bias)   // [HDIM]
{
    __shared__ float As[BK * BM];   // As[k][m]
    __shared__ float Bs[BK * BN];   // Bs[k][n]

    const int cRow = blockIdx.y;    // M tile
    const int cCol = blockIdx.x;    // N tile
    const int tid  = threadIdx.x;

    // compute-thread mapping: 16x16 threads, each owns TM x TN outputs
    const int threadCol = (tid % (BN / TN)) * TN;   // 0,8,...,120
    const int threadRow = (tid / (BN / TN)) * TM;

    // global-load mapping: each thread loads 1 float4 from A and 1 from W per k-block
    const int innerRow = tid / (BK / 4);        // 0..127
    const int innerCol = (tid % (BK / 4)) * 4;  // 0 or 4

    const float* Ab = A + (size_t)cRow * BM * KDIM;
    const float* Wb = W + (size_t)cCol * BN * KDIM;

    float acc[TM * TN];   // current Eigen k-panel chain
    float sum[TM * TN];   // folded panel sums (fp32 C-buffer semantics)
    #pragma unroll
    for (int i = 0; i < TM * TN; i++) { acc[i] = 0.0f; sum[i] = 0.0f; }
    float regM[TM], regN[TN];

    for (int kb = 0; kb < KDIM; kb += BK) {
        // ---- load A tile (transpose into As[k][m]) ----
        {
            float4 v = *reinterpret_cast<const float4*>(
                &Ab[(size_t)innerRow * KDIM + kb + innerCol]);
            As[(innerCol + 0) * BM + innerRow] = v.x;
            As[(innerCol + 1) * BM + innerRow] = v.y;
            As[(innerCol + 2) * BM + innerRow] = v.z;
            As[(innerCol + 3) * BM + innerRow] = v.w;
        }
        // ---- load W tile (transpose into Bs[k][n]) ----
        {
            float4 v = *reinterpret_cast<const float4*>(
                &Wb[(size_t)innerRow * KDIM + kb + innerCol]);
            Bs[(innerCol + 0) * BN + innerRow] = v.x;
            Bs[(innerCol + 1) * BN + innerRow] = v.y;
            Bs[(innerCol + 2) * BN + innerRow] = v.z;
            Bs[(innerCol + 3) * BN + innerRow] = v.w;
        }
        __syncthreads();

        // ---- compute: k strictly ascending, one fma chain per output ----
        #pragma unroll
        for (int k = 0; k < BK; k++) {
            #pragma unroll
            for (int i = 0; i < TM; i += 4) {
                float4 v = *reinterpret_cast<const float4*>(&As[k * BM + threadRow + i]);
                regM[i + 0] = v.x; regM[i + 1] = v.y; regM[i + 2] = v.z; regM[i + 3] = v.w;
            }
            #pragma unroll
            for (int j = 0; j < TN; j += 4) {
                float4 v = *reinterpret_cast<const float4*>(&Bs[k * BN + threadCol + j]);
                regN[j + 0] = v.x; regN[j + 1] = v.y; regN[j + 2] = v.z; regN[j + 3] = v.w;
            }
            #pragma unroll
            for (int i = 0; i < TM; i++)
                #pragma unroll
                for (int j = 0; j < TN; j++)
                    acc[i * TN + j] += regM[i] * regN[j];   // FFMA, in-order
        }
        __syncthreads();

        // ---- Eigen kc=1016 panel boundary: fold chain into C with one FADD
        const int knext = kb + BK;
        if (knext == 1016) {
            #pragma unroll
            for (int i = 0; i < TM * TN; i++) {
                sum[i] = __fadd_rn(sum[i], acc[i]);
                acc[i] = 0.0f;
            }
        }
    }

    // ---- final panel fold + bias (single FADD each, XLA separate-add op) ----
    #pragma unroll
    for (int i = 0; i < TM; i++) {
        const size_t row = (size_t)cRow * BM + threadRow + i;
        #pragma unroll
        for (int j = 0; j < TN; j += 4) {
            const int col = cCol * BN + threadCol + j;
            float4 bv = *reinterpret_cast<const float4*>(&bias[col]);
            float4 o;
            o.x = __fadd_rn(__fadd_rn(sum[i * TN + j + 0], acc[i * TN + j + 0]), bv.x);
            o.y = __fadd_rn(__fadd_rn(sum[i * TN + j + 1], acc[i * TN + j + 1]), bv.y);
            o.z = __fadd_rn(__fadd_rn(sum[i * TN + j + 2], acc[i * TN + j + 2]), bv.z);
            o.w = __fadd_rn(__fadd_rn(sum[i * TN + j + 3], acc[i * TN + j + 3]), bv.w);
            *reinterpret_cast<float4*>(&g_I[row * HDIM + col]) = o;
        }
    }
}

// ---------------------------------------------------------------------------
// LIF scan: one thread per (b,h) pair, sequential over T.
// (Fused vs unfused proven output-identical in R1 vs R4; keep unfused.)
// ---------------------------------------------------------------------------
__global__ __launch_bounds__(256) void lif_scan(
    float* __restrict__ spikes,      // [B,T,H]
    float* __restrict__ mem_final)   // [B,H]
{
    const int idx = blockIdx.x * blockDim.x + threadIdx.x;  // over B*H
    const int b = idx / HDIM;
    const int h = idx % HDIM;

    const float* Ip = g_I + (size_t)b * TDIM * HDIM + h;
    float* Sp = spikes + (size_t)b * TDIM * HDIM + h;

    float mem = 0.0f;
    #pragma unroll 8
    for (int t = 0; t < TDIM; t++) {
        mem = __fadd_rn(__fmul_rn(ALPHA, mem), Ip[(size_t)t * HDIM]);
        const bool fire = (mem >= 1.0f);
        Sp[(size_t)t * HDIM] = fire ? 1.0f : 0.0f;
        mem = fire ? 0.0f : mem;
    }
    mem_final[idx] = mem;
}

// ---------------------------------------------------------------------------
extern "C" void kernel_launch(void* const* d_in, const int* in_sizes, int n_in,
                              void* d_out, int out_size)
{
    const float* x  = (const float*)d_in[0];   // [B,T,IN]
    const float* W  = (const float*)d_in[1];   // [HID,IN]
    const float* b  = (const float*)d_in[2];   // [HID]

    float* out      = (float*)d_out;
    float* spikes   = out;                                   // B*T*H floats
    float* mem_fin  = out + (size_t)MTOT * HDIM;             // B*H floats

    // GEMM: I = x @ W^T + b   (Eigen kc=1016 panel-ordered accumulation)
    dim3 gemmGrid(HDIM / BN, MTOT / BM);   // (8, 256)
    sgemm_nt_bias_eigen<<<gemmGrid, 256>>>(x, W, b);

    // LIF scan over T
    lif_scan<<<(BDIM * HDIM) / 256, 256>>>(spikes, mem_fin);
}